// round 12
// baseline (speedup 1.0000x reference)
#include <cuda_runtime.h>
#include <cuda_fp16.h>
#include <cstdint>

#define NUM_NEURONS 8192
#define INPUT_SIZE  8192
#define BATCH       2048

#define THREADS 1024
#define NPT     8                  // neurons per thread (2 groups of 4)
#define NGROUP  (NPT / 4)          // 2
#define GRID    148                // persistent: 1 block per SM
#define PAIRS   (BATCH / 2)        // 1024 row-pairs
#define PAIR_BYTES (2 * INPUT_SIZE * 4)   // 64 KB fp32 pair

// Per-neuron collapsed coefficients: out = A + B*a1 + C*a2 + D*a1*a2
__device__ float4 g_coeff[NUM_NEURONS];

// Per-op affine coefficients (const, a1, a2, a1*a2) for the 16 logic ops.
__constant__ float4 c_op[16] = {
    {0.f,  0.f,  0.f,  0.f},   //  0: 0
    {0.f,  0.f,  0.f,  1.f},   //  1: p
    {0.f,  1.f,  0.f, -1.f},   //  2: a1 - p
    {0.f,  1.f,  0.f,  0.f},   //  3: a1
    {0.f,  0.f,  1.f, -1.f},   //  4: a2 - p
    {0.f,  0.f,  1.f,  0.f},   //  5: a2
    {0.f,  1.f,  1.f, -2.f},   //  6: a1 + a2 - 2p
    {0.f,  1.f,  1.f, -1.f},   //  7: a1 + a2 - p
    {1.f, -1.f, -1.f,  1.f},   //  8: 1 - (a1 + a2 - p)
    {1.f, -1.f, -1.f,  2.f},   //  9: 1 - (a1 + a2 - 2p)
    {1.f,  0.f, -1.f,  0.f},   // 10: 1 - a2
    {1.f,  0.f, -1.f,  1.f},   // 11: 1 - a2 + p
    {1.f, -1.f,  0.f,  0.f},   // 12: 1 - a1
    {1.f, -1.f,  0.f,  1.f},   // 13: 1 - a1 + p
    {1.f,  0.f,  0.f, -1.f},   // 14: 1 - p
    {1.f,  0.f,  0.f,  0.f},   // 15: 1
};

// ---------------------------------------------------------------------------
// Warp-parallel coefficient precompute: 16 lanes per neuron (one per op).
// ---------------------------------------------------------------------------
__global__ void coeff_kernel(const float* __restrict__ w) {
    const int gt = blockIdx.x * blockDim.x + threadIdx.x;
    const int n = gt >> 4;
    const int j = gt & 15;
    if (n >= NUM_NEURONS) return;

    const float wv = __ldg(&w[(n << 4) + j]);

    float m = wv;
#pragma unroll
    for (int o = 8; o; o >>= 1) m = fmaxf(m, __shfl_xor_sync(0xFFFFFFFFu, m, o, 16));
    const float e = __expf(wv - m);
    float s = e;
#pragma unroll
    for (int o = 8; o; o >>= 1) s += __shfl_xor_sync(0xFFFFFFFFu, s, o, 16);
    const float p = e / s;

    const float4 c = c_op[j];
    float A = p * c.x, B = p * c.y, C = p * c.z, D = p * c.w;
#pragma unroll
    for (int o = 8; o; o >>= 1) {
        A += __shfl_xor_sync(0xFFFFFFFFu, A, o, 16);
        B += __shfl_xor_sync(0xFFFFFFFFu, B, o, 16);
        C += __shfl_xor_sync(0xFFFFFFFFu, C, o, 16);
        D += __shfl_xor_sync(0xFFFFFFFFu, D, o, 16);
    }
    if (j == 0) g_coeff[n] = make_float4(A, B, C, D);
}

// ---------------------------------------------------------------------------
// PTX helpers (mbarrier + 1D TMA bulk copy)
// ---------------------------------------------------------------------------
__device__ __forceinline__ uint32_t smem_u32(const void* p) {
    uint32_t a;
    asm("{ .reg .u64 t; cvta.to.shared.u64 t, %1; cvt.u32.u64 %0, t; }"
        : "=r"(a) : "l"(p));
    return a;
}
__device__ __forceinline__ void mbar_init(uint32_t m, uint32_t cnt) {
    asm volatile("mbarrier.init.shared.b64 [%0], %1;" :: "r"(m), "r"(cnt) : "memory");
}
__device__ __forceinline__ void mbar_expect_tx(uint32_t m, uint32_t bytes) {
    asm volatile("mbarrier.arrive.expect_tx.shared.b64 _, [%0], %1;"
                 :: "r"(m), "r"(bytes) : "memory");
}
__device__ __forceinline__ void mbar_wait(uint32_t m, uint32_t phase) {
    asm volatile(
        "{\n\t.reg .pred P;\n\t"
        "WL_%=:\n\t"
        "mbarrier.try_wait.parity.acquire.cta.shared::cta.b64 P, [%0], %1, 0x989680;\n\t"
        "@P bra WD_%=;\n\t"
        "bra WL_%=;\n\t"
        "WD_%=:\n\t}"
        :: "r"(m), "r"(phase) : "memory");
}
__device__ __forceinline__ void tma_bulk_g2s(uint32_t dst_smem, const void* src,
                                             uint32_t bytes, uint32_t mbar) {
    asm volatile(
        "cp.async.bulk.shared::cluster.global.mbarrier::complete_tx::bytes "
        "[%0], [%1], %2, [%3];"
        :: "r"(dst_smem), "l"(src), "r"(bytes), "r"(mbar) : "memory");
}

__device__ __forceinline__ unsigned h2u(__half2 h) {
    return *reinterpret_cast<unsigned*>(&h);
}

// Vectorized convert: fp32 pair buffer -> half2 {row0,row1} table.
// Conflict-free (consecutive lanes, consecutive 16B). 2 iterations/thread.
__device__ __forceinline__ void convert_pair(const float* bf, __half2* xh, int tid) {
    const float4* b4 = reinterpret_cast<const float4*>(bf);
    uint4* x4 = reinterpret_cast<uint4*>(xh);
#pragma unroll
    for (int i = 0; i < 2; i++) {
        const int c = i * THREADS + tid;          // float4 column group
        float4 r0 = b4[c];                        // row0 cols 4c..4c+3
        float4 r1 = b4[c + INPUT_SIZE / 4];       // row1 cols 4c..4c+3
        x4[c] = make_uint4(h2u(__floats2half2_rn(r0.x, r1.x)),
                           h2u(__floats2half2_rn(r0.y, r1.y)),
                           h2u(__floats2half2_rn(r0.z, r1.z)),
                           h2u(__floats2half2_rn(r0.w, r1.w)));
    }
}

// ---------------------------------------------------------------------------
// Persistent main kernel. grid=148, 1 block/SM, 1024 threads.
// ONE barrier per pair: iteration k converts pair k+1 (into xh[(k+1)&1],
// disjoint from the gather table xh[k&1]) and then gathers/computes pair k,
// all in one instruction window — the conflict-free convert wavefronts fill
// crossbar bubbles left by gather conflicts. TMA k+2 is issued into
// fbuf[k&1], whose last reader (convert of pair k) finished behind the
// barrier that ended iteration k-1.
// ---------------------------------------------------------------------------
__global__ __launch_bounds__(THREADS, 1) void logic_kernel(
    const float* __restrict__ x,
    const int*   __restrict__ idx,
    float* __restrict__ out)
{
    extern __shared__ __align__(128) char smem[];
    float*   fbuf0 = reinterpret_cast<float*>(smem);                  // 64 KB
    float*   fbuf1 = reinterpret_cast<float*>(smem + PAIR_BYTES);     // 64 KB
    __half2* xh0 = reinterpret_cast<__half2*>(smem + 2 * PAIR_BYTES); // 32 KB
    __half2* xh1 = xh0 + INPUT_SIZE;                                  // 32 KB
    const uint32_t mbar0 = smem_u32(smem + 2 * PAIR_BYTES + 2 * INPUT_SIZE * 4);
    const uint32_t mbar1 = mbar0 + 8;

    const int tid = threadIdx.x;
    const int bid = blockIdx.x;

    // --- Preload idx (packed u16 pairs) + coefficients into registers ---
    uint32_t pidx[NPT];
    float4   cf[NPT];
    const int4* idx4 = reinterpret_cast<const int4*>(idx);
#pragma unroll
    for (int g = 0; g < NGROUP; g++) {
        int nbase = g * (4 * THREADS) + tid * 4;
        int4 ia = __ldg(&idx4[nbase / 2]);
        int4 ib = __ldg(&idx4[nbase / 2 + 1]);
        pidx[g * 4 + 0] = (uint32_t)ia.x | ((uint32_t)ia.y << 16);
        pidx[g * 4 + 1] = (uint32_t)ia.z | ((uint32_t)ia.w << 16);
        pidx[g * 4 + 2] = (uint32_t)ib.x | ((uint32_t)ib.y << 16);
        pidx[g * 4 + 3] = (uint32_t)ib.z | ((uint32_t)ib.w << 16);
#pragma unroll
        for (int u = 0; u < 4; u++) cf[g * 4 + u] = g_coeff[nbase + u];
    }

    if (tid == 0) { mbar_init(mbar0, 1); mbar_init(mbar1, 1); }
    __syncthreads();

    const int npairs = (PAIRS - bid + GRID - 1) / GRID;   // 6 or 7

    // --- Prologue: TMA pairs 0 and 1; convert pair 0 ---
    if (tid == 0) {
        mbar_expect_tx(mbar0, PAIR_BYTES);
        tma_bulk_g2s(smem_u32(fbuf0), x + (size_t)bid * 2 * INPUT_SIZE,
                     PAIR_BYTES, mbar0);
        if (npairs > 1) {
            mbar_expect_tx(mbar1, PAIR_BYTES);
            tma_bulk_g2s(smem_u32(fbuf1), x + (size_t)(bid + GRID) * 2 * INPUT_SIZE,
                         PAIR_BYTES, mbar1);
        }
    }
    __syncthreads();               // mbar inits + issues visible

    mbar_wait(mbar0, 0);           // pair 0 data
    convert_pair(fbuf0, xh0, tid);
    __syncthreads();               // xh0 ready for everyone

    uint32_t phases = 2;           // mbar0 next parity=1; mbar1 next parity=0
                                   // bit0 = mbar0 parity, bit1 = mbar1 parity... see below
    // track parities separately:
    uint32_t par0 = 1, par1 = 0;
    (void)phases;

    for (int k = 0; k < npairs; k++) {
        const int b = k & 1;
        const __half2* cur = b ? xh1 : xh0;
        __half2*       nxt = b ? xh0 : xh1;
        const float*   nfb = b ? fbuf0 : fbuf1;   // fbuf[(k+1)&1]

        // --- Convert pair k+1 (waits its TMA; disjoint from cur) ---
        if (k + 1 < npairs) {
            if ((k + 1) & 1) { mbar_wait(mbar1, par1); par1 ^= 1; }
            else             { mbar_wait(mbar0, par0); par0 ^= 1; }
            convert_pair(nfb, nxt, tid);
        }

        // --- Issue TMA k+2 into fbuf[k&1] (its convert ended behind last barrier) ---
        if (tid == 0 && k + 2 < npairs) {
            const uint32_t mb = b ? mbar1 : mbar0;
            mbar_expect_tx(mb, PAIR_BYTES);
            tma_bulk_g2s(smem_u32(b ? fbuf1 : fbuf0),
                         x + (size_t)(bid + (k + 2) * GRID) * 2 * INPUT_SIZE,
                         PAIR_BYTES, mb);
        }

        // --- Gather + compute pair k ---
        const int p = bid + k * GRID;
        float4* o0 = reinterpret_cast<float4*>(out + (size_t)(2 * p)     * NUM_NEURONS);
        float4* o1 = reinterpret_cast<float4*>(out + (size_t)(2 * p + 1) * NUM_NEURONS);

#pragma unroll
        for (int g = 0; g < NGROUP; g++) {
            float4 r0, r1;
            float* q0 = reinterpret_cast<float*>(&r0);
            float* q1 = reinterpret_cast<float*>(&r1);
#pragma unroll
            for (int u = 0; u < 4; u++) {
                const uint32_t pk = pidx[g * 4 + u];
                const float2 a1 = __half22float2(cur[pk & 0xFFFFu]);
                const float2 a2 = __half22float2(cur[pk >> 16]);
                const float4 c = cf[g * 4 + u];
                q0[u] = fmaf(a1.x, fmaf(a2.x, c.w, c.y), fmaf(a2.x, c.z, c.x));
                q1[u] = fmaf(a1.y, fmaf(a2.y, c.w, c.y), fmaf(a2.y, c.z, c.x));
            }
            const int o = g * THREADS + tid;
            o0[o] = r0;
            o1[o] = r1;
        }

        __syncthreads();   // gathers of k done (frees xh[k&1] + fbuf[(k+1)&1] rule),
                           // convert of k+1 visible to all
    }
}

extern "C" void kernel_launch(void* const* d_in, const int* in_sizes, int n_in,
                              void* d_out, int out_size) {
    const float* x    = (const float*)d_in[0];   // [2048, 8192] f32
    const float* w    = (const float*)d_in[1];   // [8192, 16]   f32
    const int*   conn = (const int*)d_in[2];     // [8192, 2]    i32
    float* out = (float*)d_out;                  // [2048, 8192] f32

    const int smem = 2 * PAIR_BYTES + 2 * INPUT_SIZE * 4 + 16;  // 192 KB + mbars
    cudaFuncSetAttribute(logic_kernel,
                         cudaFuncAttributeMaxDynamicSharedMemorySize, smem);

    coeff_kernel<<<(NUM_NEURONS * 16) / 256, 256>>>(w);
    logic_kernel<<<GRID, THREADS, smem>>>(x, conn, out);
}

// round 13
// speedup vs baseline: 1.1188x; 1.1188x over previous
#include <cuda_runtime.h>
#include <cstdint>

#define NUM_NEURONS 8192
#define INPUT_SIZE  8192
#define BATCH       2048

#define THREADS 512
#define NPT     16                 // neurons per thread (4 groups of 4)
#define GRID    148                // persistent: 1 block per SM
#define PAIRS   (BATCH / 2)        // 1024 row-pairs
#define PAIR_BYTES (2 * INPUT_SIZE * 4)   // 64 KB

// Per-neuron collapsed coefficients: out = A + B*a1 + C*a2 + D*a1*a2
__device__ float4 g_coeff[NUM_NEURONS];

// Per-op affine coefficients (const, a1, a2, a1*a2) for the 16 logic ops.
__constant__ float4 c_op[16] = {
    {0.f,  0.f,  0.f,  0.f},   //  0: 0
    {0.f,  0.f,  0.f,  1.f},   //  1: p
    {0.f,  1.f,  0.f, -1.f},   //  2: a1 - p
    {0.f,  1.f,  0.f,  0.f},   //  3: a1
    {0.f,  0.f,  1.f, -1.f},   //  4: a2 - p
    {0.f,  0.f,  1.f,  0.f},   //  5: a2
    {0.f,  1.f,  1.f, -2.f},   //  6: a1 + a2 - 2p
    {0.f,  1.f,  1.f, -1.f},   //  7: a1 + a2 - p
    {1.f, -1.f, -1.f,  1.f},   //  8: 1 - (a1 + a2 - p)
    {1.f, -1.f, -1.f,  2.f},   //  9: 1 - (a1 + a2 - 2p)
    {1.f,  0.f, -1.f,  0.f},   // 10: 1 - a2
    {1.f,  0.f, -1.f,  1.f},   // 11: 1 - a2 + p
    {1.f, -1.f,  0.f,  0.f},   // 12: 1 - a1
    {1.f, -1.f,  0.f,  1.f},   // 13: 1 - a1 + p
    {1.f,  0.f,  0.f, -1.f},   // 14: 1 - p
    {1.f,  0.f,  0.f,  0.f},   // 15: 1
};

// ---------------------------------------------------------------------------
// Warp-parallel coefficient precompute: 16 lanes per neuron (one per op).
// One coalesced load + one exp per lane; softmax and the coefficient dot
// products are width-16 shuffle reductions. 131072 threads -> full chip.
// ---------------------------------------------------------------------------
__global__ void coeff_kernel(const float* __restrict__ w) {
    const int gt = blockIdx.x * blockDim.x + threadIdx.x;
    const int n = gt >> 4;
    const int j = gt & 15;
    if (n >= NUM_NEURONS) return;

    const float wv = __ldg(&w[(n << 4) + j]);

    float m = wv;
#pragma unroll
    for (int o = 8; o; o >>= 1) m = fmaxf(m, __shfl_xor_sync(0xFFFFFFFFu, m, o, 16));
    const float e = __expf(wv - m);
    float s = e;
#pragma unroll
    for (int o = 8; o; o >>= 1) s += __shfl_xor_sync(0xFFFFFFFFu, s, o, 16);
    const float p = e / s;

    const float4 c = c_op[j];
    float A = p * c.x, B = p * c.y, C = p * c.z, D = p * c.w;
#pragma unroll
    for (int o = 8; o; o >>= 1) {
        A += __shfl_xor_sync(0xFFFFFFFFu, A, o, 16);
        B += __shfl_xor_sync(0xFFFFFFFFu, B, o, 16);
        C += __shfl_xor_sync(0xFFFFFFFFu, C, o, 16);
        D += __shfl_xor_sync(0xFFFFFFFFu, D, o, 16);
    }
    if (j == 0) g_coeff[n] = make_float4(A, B, C, D);
}

// ---------------------------------------------------------------------------
// PTX helpers (mbarrier + 1D TMA bulk copy)
// ---------------------------------------------------------------------------
__device__ __forceinline__ uint32_t smem_u32(const void* p) {
    uint32_t a;
    asm("{ .reg .u64 t; cvta.to.shared.u64 t, %1; cvt.u32.u64 %0, t; }"
        : "=r"(a) : "l"(p));
    return a;
}
__device__ __forceinline__ void mbar_init(uint32_t m, uint32_t cnt) {
    asm volatile("mbarrier.init.shared.b64 [%0], %1;" :: "r"(m), "r"(cnt) : "memory");
}
__device__ __forceinline__ void mbar_expect_tx(uint32_t m, uint32_t bytes) {
    asm volatile("mbarrier.arrive.expect_tx.shared.b64 _, [%0], %1;"
                 :: "r"(m), "r"(bytes) : "memory");
}
__device__ __forceinline__ void mbar_wait(uint32_t m, uint32_t phase) {
    asm volatile(
        "{\n\t.reg .pred P;\n\t"
        "WL_%=:\n\t"
        "mbarrier.try_wait.parity.acquire.cta.shared::cta.b64 P, [%0], %1, 0x989680;\n\t"
        "@P bra WD_%=;\n\t"
        "bra WL_%=;\n\t"
        "WD_%=:\n\t}"
        :: "r"(m), "r"(phase) : "memory");
}
__device__ __forceinline__ void tma_bulk_g2s(uint32_t dst_smem, const void* src,
                                             uint32_t bytes, uint32_t mbar) {
    asm volatile(
        "cp.async.bulk.shared::cluster.global.mbarrier::complete_tx::bytes "
        "[%0], [%1], %2, [%3];"
        :: "r"(dst_smem), "l"(src), "r"(bytes), "r"(mbar) : "memory");
}

// ---------------------------------------------------------------------------
// Persistent main kernel (R5 structure verbatim — best measured logic-kernel
// time of the session: 23.0us). grid=148, 1 block/SM (132KB smem). Each block
// processes row-pairs p = bid, bid+148, ... with TMA double buffering:
// while computing pair k from buffer k%2, the TMA for pair k+2 streams into
// the other buffer with ZERO LSU work. idx+coeff live in registers for the
// whole kernel (thread t owns neurons {g*2048 + 4t .. +3 : g=0..3}).
// ---------------------------------------------------------------------------
__global__ __launch_bounds__(THREADS, 1) void logic_kernel(
    const float* __restrict__ x,
    const int*   __restrict__ idx,
    float* __restrict__ out)
{
    extern __shared__ __align__(128) char smem[];
    float* buf0 = reinterpret_cast<float*>(smem);                 // 64 KB
    float* buf1 = reinterpret_cast<float*>(smem + PAIR_BYTES);    // 64 KB
    const uint32_t mbar0 = smem_u32(smem + 2 * PAIR_BYTES);
    const uint32_t mbar1 = mbar0 + 8;

    const int tid = threadIdx.x;
    const int bid = blockIdx.x;

    // --- Preload idx (packed u16 pairs) + coefficients into registers ---
    uint32_t pidx[NPT];
    float4   cf[NPT];
    const int4* idx4 = reinterpret_cast<const int4*>(idx);  // 2 neurons per int4
#pragma unroll
    for (int g = 0; g < 4; g++) {
        int nbase = g * 2048 + tid * 4;            // 4 consecutive neurons
        int4 ia = __ldg(&idx4[nbase / 2]);         // neurons nbase, nbase+1
        int4 ib = __ldg(&idx4[nbase / 2 + 1]);     // neurons nbase+2, nbase+3
        pidx[g * 4 + 0] = (uint32_t)ia.x | ((uint32_t)ia.y << 16);
        pidx[g * 4 + 1] = (uint32_t)ia.z | ((uint32_t)ia.w << 16);
        pidx[g * 4 + 2] = (uint32_t)ib.x | ((uint32_t)ib.y << 16);
        pidx[g * 4 + 3] = (uint32_t)ib.z | ((uint32_t)ib.w << 16);
#pragma unroll
        for (int u = 0; u < 4; u++) cf[g * 4 + u] = g_coeff[nbase + u];
    }

    if (tid == 0) { mbar_init(mbar0, 1); mbar_init(mbar1, 1); }
    __syncthreads();

    const int npairs = (PAIRS - bid + GRID - 1) / GRID;   // 6 or 7

    // --- Prologue: issue first two TMA loads ---
    if (tid == 0) {
        if (npairs > 0) {
            mbar_expect_tx(mbar0, PAIR_BYTES);
            tma_bulk_g2s(smem_u32(buf0), x + (size_t)bid * 2 * INPUT_SIZE,
                         PAIR_BYTES, mbar0);
        }
        if (npairs > 1) {
            mbar_expect_tx(mbar1, PAIR_BYTES);
            tma_bulk_g2s(smem_u32(buf1), x + (size_t)(bid + GRID) * 2 * INPUT_SIZE,
                         PAIR_BYTES, mbar1);
        }
    }

    uint32_t phases = 0;   // bit b = current wait parity of buffer b

    for (int k = 0; k < npairs; k++) {
        const int b = k & 1;
        const float* xs0 = b ? buf1 : buf0;
        const float* xs1 = xs0 + INPUT_SIZE;
        const uint32_t mb = b ? mbar1 : mbar0;

        mbar_wait(mb, (phases >> b) & 1u);
        phases ^= (1u << b);

        const int p = bid + k * GRID;
        float4* o0 = reinterpret_cast<float4*>(out + (size_t)(2 * p)     * NUM_NEURONS);
        float4* o1 = reinterpret_cast<float4*>(out + (size_t)(2 * p + 1) * NUM_NEURONS);

#pragma unroll
        for (int g = 0; g < 4; g++) {
            float4 r0, r1;
            float* q0 = reinterpret_cast<float*>(&r0);
            float* q1 = reinterpret_cast<float*>(&r1);
#pragma unroll
            for (int u = 0; u < 4; u++) {
                const uint32_t pk = pidx[g * 4 + u];
                const int i1 = pk & 0xFFFFu;
                const int i2 = pk >> 16;
                const float a10 = xs0[i1], a20 = xs0[i2];
                const float a11 = xs1[i1], a21 = xs1[i2];
                const float4 c = cf[g * 4 + u];
                q0[u] = fmaf(a10, fmaf(a20, c.w, c.y), fmaf(a20, c.z, c.x));
                q1[u] = fmaf(a11, fmaf(a21, c.w, c.y), fmaf(a21, c.z, c.x));
            }
            const int o = g * THREADS + tid;   // coalesced float4 stores
            o0[o] = r0;
            o1[o] = r1;
        }

        __syncthreads();   // everyone done reading buffer b

        if (tid == 0 && k + 2 < npairs) {
            mbar_expect_tx(mb, PAIR_BYTES);
            tma_bulk_g2s(smem_u32(b ? buf1 : buf0),
                         x + (size_t)(bid + (k + 2) * GRID) * 2 * INPUT_SIZE,
                         PAIR_BYTES, mb);
        }
    }
}

extern "C" void kernel_launch(void* const* d_in, const int* in_sizes, int n_in,
                              void* d_out, int out_size) {
    const float* x    = (const float*)d_in[0];   // [2048, 8192] f32
    const float* w    = (const float*)d_in[1];   // [8192, 16]   f32
    const int*   conn = (const int*)d_in[2];     // [8192, 2]    i32
    float* out = (float*)d_out;                  // [2048, 8192] f32

    const int smem = 2 * PAIR_BYTES + 16;        // 128 KB buffers + 2 mbarriers
    cudaFuncSetAttribute(logic_kernel,
                         cudaFuncAttributeMaxDynamicSharedMemorySize, smem);

    coeff_kernel<<<(NUM_NEURONS * 16) / 256, 256>>>(w);
    logic_kernel<<<GRID, THREADS, smem>>>(x, conn, out);
}